// round 2
// baseline (speedup 1.0000x reference)
#include <cuda_runtime.h>

#define NA 100000
#define NP 3200000
#define FA 75
#define FPR 14
#define HH 50
#define FO 50

// ---------------- scratch (device globals; no allocs allowed) ----------------
__device__ float g_AA[NA * HH];   // relu(af @ W_AA^T + b_AA)
__device__ float g_X1[NA * HH];   // af @ W_AP[:, :75]^T   (no bias)
__device__ float g_X2[NA * HH];   // af @ W_AP[:, 75:]^T   (no bias)
__device__ float g_PA[NA * HH];   // segment-summed relu(pf @ W_PA^T + b_PA)

__device__ __forceinline__ float relu_(float x) { return fmaxf(x, 0.0f); }

// =====================================================================
// K1: atom-side precompute.  grid = (ceil(NA/64), 3), 256 threads.
//   mat 0: g_AA = relu(af @ W_AA^T + b_AA)   (also zeroes g_PA)
//   mat 1: g_X1 = af @ W1^T
//   mat 2: g_X2 = af @ W2^T
// =====================================================================
__global__ __launch_bounds__(256) void atom_pre_kernel(
    const float* __restrict__ af,
    const float* __restrict__ W_AA, const float* __restrict__ b_AA,
    const float* __restrict__ W_AP)
{
    __shared__ __align__(16) float AsT[76 * 68];
    __shared__ __align__(16) float BsT[76 * 68];
    __shared__ float bsh[64];

    const int mat = blockIdx.y;
    const int abase = blockIdx.x * 64;
    const int tid = threadIdx.x;

    for (int idx = tid; idx < 64 * 76; idx += 256) {
        int k = idx % 76, m = idx / 76;
        int a = abase + m;
        AsT[k * 68 + m] = (k < FA && a < NA) ? af[a * FA + k] : 0.0f;
    }
    const float* W; int ws, wo;
    if (mat == 0) { W = W_AA; ws = FA;     wo = 0; }
    else          { W = W_AP; ws = 2 * FA; wo = (mat == 1) ? 0 : FA; }
    for (int idx = tid; idx < 64 * 76; idx += 256) {
        int k = idx % 76, o = idx / 76;
        BsT[k * 68 + o] = (k < FA && o < HH) ? W[o * ws + wo + k] : 0.0f;
    }
    if (mat == 0 && tid < 64) bsh[tid] = (tid < HH) ? b_AA[tid] : 0.0f;
    if (mat == 0) {
        for (int idx = tid; idx < 64 * HH; idx += 256) {
            int m = idx / HH, o = idx % HH;
            int a = abase + m;
            if (a < NA) g_PA[a * HH + o] = 0.0f;
        }
    }
    __syncthreads();

    const int tm = tid >> 4, tn = tid & 15;
    const int m0 = tm * 4, n0 = tn * 4;
    float acc[4][4];
#pragma unroll
    for (int r = 0; r < 4; r++)
#pragma unroll
        for (int c = 0; c < 4; c++) acc[r][c] = 0.0f;

#pragma unroll 4
    for (int k = 0; k < 76; k++) {
        float4 a4 = *(const float4*)&AsT[k * 68 + m0];
        float4 b4 = *(const float4*)&BsT[k * 68 + n0];
        float av[4] = {a4.x, a4.y, a4.z, a4.w};
        float bv[4] = {b4.x, b4.y, b4.z, b4.w};
#pragma unroll
        for (int r = 0; r < 4; r++)
#pragma unroll
            for (int c = 0; c < 4; c++) acc[r][c] += av[r] * bv[c];
    }

    float* dst = (mat == 0) ? g_AA : ((mat == 1) ? g_X1 : g_X2);
#pragma unroll
    for (int r = 0; r < 4; r++) {
        int a = abase + m0 + r;
        if (a < NA) {
#pragma unroll
            for (int c = 0; c < 4; c++) {
                int o = n0 + c;
                if (o < HH) {
                    float v = acc[r][c];
                    if (mat == 0) v = relu_(v + bsh[o]);
                    dst[a * HH + o] = v;
                }
            }
        }
    }
}

// =====================================================================
// K2 (megakernel), 128-pair tiles. See Round 0 notes.
// FIX (R1): run-head detection must force a head at t=0 of every tile so
// runs spanning tile boundaries get both portions atomically accumulated.
// =====================================================================
#define CTS 132
#define WTS 68
#define PAIR_SMEM_FLOATS (104*CTS + 104*WTS + 16*CTS + 16*WTS + 16*WTS + 4*52 + 256 + 132 + 128 + 4)
#define PAIR_SMEM_BYTES  (PAIR_SMEM_FLOATS * 4)

__global__ __launch_bounds__(256, 2) void pair_kernel(
    const float* __restrict__ pf,
    const int*   __restrict__ split,
    const int*   __restrict__ atp,
    const float* __restrict__ W_PA, const float* __restrict__ b_PA,
    const float* __restrict__ W_PP, const float* __restrict__ b_PP,
    const float* __restrict__ W_P,  const float* __restrict__ b_P,
    const float* __restrict__ b_AP,
    float* __restrict__ outP)
{
    extern __shared__ __align__(16) float sm[];
    float* CT   = sm;                       // [104][CTS]
    float* WT   = CT + 104 * CTS;           // [104][WTS]
    float* pfT  = WT + 104 * WTS;           // [16][CTS]
    float* WpaT = pfT + 16 * CTS;           // [16][WTS]
    float* WppT = WpaT + 16 * WTS;          // [16][WTS]
    float* sbAP = WppT + 16 * WTS;          // 52
    float* sbPP = sbAP + 52;
    float* sbPA = sbPP + 52;
    float* sbP  = sbPA + 52;
    int* sidx   = (int*)(sbP + 52);         // 256
    int* spsv   = sidx + 256;               // 132
    int* sheads = spsv + 132;               // 128
    int* snh    = sheads + 128;             // 1

    const int p0  = blockIdx.x * 128;
    const int tid = threadIdx.x;

    // ---------------- P0: staging ----------------
    for (int idx = tid; idx < 128 * 16; idx += 256) {
        int kk = idx & 15, p = idx >> 4;
        pfT[kk * CTS + p] = (kk < FPR) ? __ldcs(&pf[(p0 + p) * FPR + kk]) : 0.0f;
    }
    for (int idx = tid; idx < 64 * 104; idx += 256) {
        int k = idx % 104, o = idx / 104;
        WT[k * WTS + o] = (k < 2 * HH && o < FO) ? W_P[o * 2 * HH + k] : 0.0f;
    }
    for (int idx = tid; idx < 64 * 16; idx += 256) {
        int k = idx & 15, o = idx >> 4;
        bool v = (k < FPR && o < HH);
        WpaT[k * WTS + o] = v ? W_PA[o * FPR + k] : 0.0f;
        WppT[k * WTS + o] = v ? W_PP[o * FPR + k] : 0.0f;
    }
    if (tid < 52) {
        float vAP = (tid < HH) ? b_AP[tid] : 0.0f;
        float vPP = (tid < HH) ? b_PP[tid] : 0.0f;
        float vPA = (tid < HH) ? b_PA[tid] : 0.0f;
        float vP  = (tid < FO) ? b_P[tid]  : 0.0f;
        sbAP[tid] = vAP; sbPP[tid] = vPP; sbPA[tid] = vPA; sbP[tid] = vP;
    }
    sidx[tid] = atp[p0 * 2 + tid];
    if (tid < 129) {
        // spsv[0] = -1 ALWAYS: forces a run head at t=0 of every tile, so
        // runs crossing tile boundaries are accumulated from both sides.
        spsv[tid] = (tid == 0) ? -1 : split[p0 + tid - 1];
    }
    if (tid == 0) *snh = 0;
    __syncthreads();

    const int tm = tid >> 4, tn = tid & 15;
    const int m0 = tm * 8, n0 = tn * 4;

    // ---------------- P1: PA (into CT rows [0,50) as scratch) ----------------
    {
        float acc[8][4];
#pragma unroll
        for (int r = 0; r < 8; r++)
#pragma unroll
            for (int c = 0; c < 4; c++) acc[r][c] = 0.0f;
#pragma unroll 4
        for (int k = 0; k < 16; k++) {
            float4 b4 = *(const float4*)&WpaT[k * WTS + n0];
            float4 a0 = *(const float4*)&pfT[k * CTS + m0];
            float4 a1 = *(const float4*)&pfT[k * CTS + m0 + 4];
            float av[8] = {a0.x, a0.y, a0.z, a0.w, a1.x, a1.y, a1.z, a1.w};
            float bv[4] = {b4.x, b4.y, b4.z, b4.w};
#pragma unroll
            for (int r = 0; r < 8; r++)
#pragma unroll
                for (int c = 0; c < 4; c++) acc[r][c] += av[r] * bv[c];
        }
#pragma unroll
        for (int c = 0; c < 4; c++) {
            int o = n0 + c;
            if (o < HH) {
                float b = sbPA[o];
#pragma unroll
                for (int r = 0; r < 8; r++)
                    CT[o * CTS + m0 + r] = relu_(acc[r][c] + b);
            }
        }
    }
    __syncthreads();

    // ---------------- P2: sorted-run reduce + atomics into g_PA ----------------
    if (tid < 128) {
        if (spsv[tid + 1] != spsv[tid]) {
            int pos = atomicAdd(snh, 1);
            sheads[pos] = tid;
        }
    }
    __syncthreads();
    {
        int nh = *snh;
        for (int t = tid; t < nh * 64; t += 256) {
            int o = t & 63, hi = t >> 6;
            if (o < HH) {
                int h = sheads[hi];
                int seg = spsv[h + 1];
                float s = 0.0f;
                int q = h;
                while (q < 128 && spsv[q + 1] == seg) { s += CT[o * CTS + q]; q++; }
                atomicAdd(&g_PA[seg * HH + o], s);
            }
        }
    }
    __syncthreads();

    // ---------------- P3: S gathers + PP GEMM ----------------
    for (int idx = tid; idx < 128 * 25; idx += 256) {
        int p = idx / 25, k2 = idx % 25;
        int k = k2 * 2;
        int i = sidx[2 * p], j = sidx[2 * p + 1];
        float2 x1i = *(const float2*)&g_X1[i * HH + k];
        float2 x2j = *(const float2*)&g_X2[j * HH + k];
        float2 x1j = *(const float2*)&g_X1[j * HH + k];
        float2 x2i = *(const float2*)&g_X2[i * HH + k];
        float b0 = sbAP[k], b1 = sbAP[k + 1];
        float s0 = relu_(x1i.x + x2j.x + b0) + relu_(x1j.x + x2i.x + b0);
        float s1 = relu_(x1i.y + x2j.y + b1) + relu_(x1j.y + x2i.y + b1);
        CT[k * CTS + p]       = s0;
        CT[(k + 1) * CTS + p] = s1;
    }
    for (int idx = tid; idx < 4 * 128; idx += 256)
        CT[(100 + (idx >> 7)) * CTS + (idx & 127)] = 0.0f;
    {
        float acc[8][4];
#pragma unroll
        for (int r = 0; r < 8; r++)
#pragma unroll
            for (int c = 0; c < 4; c++) acc[r][c] = 0.0f;
#pragma unroll 4
        for (int k = 0; k < 16; k++) {
            float4 b4 = *(const float4*)&WppT[k * WTS + n0];
            float4 a0 = *(const float4*)&pfT[k * CTS + m0];
            float4 a1 = *(const float4*)&pfT[k * CTS + m0 + 4];
            float av[8] = {a0.x, a0.y, a0.z, a0.w, a1.x, a1.y, a1.z, a1.w};
            float bv[4] = {b4.x, b4.y, b4.z, b4.w};
#pragma unroll
            for (int r = 0; r < 8; r++)
#pragma unroll
                for (int c = 0; c < 4; c++) acc[r][c] += av[r] * bv[c];
        }
#pragma unroll
        for (int c = 0; c < 4; c++) {
            int o = n0 + c;
            if (o < HH) {
                float b = sbPP[o];
#pragma unroll
                for (int r = 0; r < 8; r++)
                    CT[(HH + o) * CTS + m0 + r] = relu_(acc[r][c] + b);
            }
        }
    }
    __syncthreads();

    // ---------------- P4: P = relu([S|PP] @ W_P^T + b_P) ----------------
    {
        float acc[8][4];
#pragma unroll
        for (int r = 0; r < 8; r++)
#pragma unroll
            for (int c = 0; c < 4; c++) acc[r][c] = 0.0f;
#pragma unroll 4
        for (int k = 0; k < 104; k++) {
            float4 b4 = *(const float4*)&WT[k * WTS + n0];
            float4 a0 = *(const float4*)&CT[k * CTS + m0];
            float4 a1 = *(const float4*)&CT[k * CTS + m0 + 4];
            float av[8] = {a0.x, a0.y, a0.z, a0.w, a1.x, a1.y, a1.z, a1.w};
            float bv[4] = {b4.x, b4.y, b4.z, b4.w};
#pragma unroll
            for (int r = 0; r < 8; r++)
#pragma unroll
                for (int c = 0; c < 4; c++) acc[r][c] += av[r] * bv[c];
        }
        if (n0 < FO) {
            float bb[4];
#pragma unroll
            for (int c = 0; c < 4; c++) bb[c] = sbP[n0 + c];
#pragma unroll
            for (int r = 0; r < 8; r++) {
                size_t p = (size_t)(p0 + m0 + r);
                float v0 = relu_(acc[r][0] + bb[0]);
                float v1 = relu_(acc[r][1] + bb[1]);
                float* dst = &outP[p * FO + n0];
                __stcs((float2*)dst, make_float2(v0, v1));
                if (n0 + 3 < FO) {
                    float v2 = relu_(acc[r][2] + bb[2]);
                    float v3 = relu_(acc[r][3] + bb[3]);
                    __stcs((float2*)(dst + 2), make_float2(v2, v3));
                }
            }
        }
    }
}

// =====================================================================
// K3: A = relu(concat([AA, PAseg]) @ W_A^T + b_A)
// =====================================================================
#define K3_SMEM_FLOATS (104*68 * 2 + 64)
#define K3_SMEM_BYTES  (K3_SMEM_FLOATS * 4)

__global__ __launch_bounds__(256) void atom_out_kernel(
    const float* __restrict__ W_A, const float* __restrict__ b_A,
    float* __restrict__ outA)
{
    extern __shared__ __align__(16) float sm3[];
    float* CcT = sm3;             // [104][68]
    float* BsT = CcT + 104 * 68;  // [104][68]
    float* bsh = BsT + 104 * 68;  // 64

    const int abase = blockIdx.x * 64;
    const int tid = threadIdx.x;

    for (int idx = tid; idx < 64 * 104; idx += 256) {
        int k = idx % 104, m = idx / 104;
        int a = abase + m;
        float v = 0.0f;
        if (a < NA) {
            if (k < HH)          v = g_AA[a * HH + k];
            else if (k < 2 * HH) v = g_PA[a * HH + (k - HH)];
        }
        CcT[k * 68 + m] = v;
    }
    for (int idx = tid; idx < 64 * 104; idx += 256) {
        int k = idx % 104, o = idx / 104;
        BsT[k * 68 + o] = (k < 2 * HH && o < FO) ? W_A[o * 2 * HH + k] : 0.0f;
    }
    if (tid < 64) bsh[tid] = (tid < FO) ? b_A[tid] : 0.0f;
    __syncthreads();

    const int tm = tid >> 4, tn = tid & 15;
    const int m0 = tm * 4, n0 = tn * 4;
    float acc[4][4];
#pragma unroll
    for (int r = 0; r < 4; r++)
#pragma unroll
        for (int c = 0; c < 4; c++) acc[r][c] = 0.0f;

#pragma unroll 4
    for (int k = 0; k < 104; k++) {
        float4 a4 = *(const float4*)&CcT[k * 68 + m0];
        float4 b4 = *(const float4*)&BsT[k * 68 + n0];
        float av[4] = {a4.x, a4.y, a4.z, a4.w};
        float bv[4] = {b4.x, b4.y, b4.z, b4.w};
#pragma unroll
        for (int r = 0; r < 4; r++)
#pragma unroll
            for (int c = 0; c < 4; c++) acc[r][c] += av[r] * bv[c];
    }
#pragma unroll
    for (int r = 0; r < 4; r++) {
        int a = abase + m0 + r;
        if (a < NA) {
#pragma unroll
            for (int c = 0; c < 4; c++) {
                int o = n0 + c;
                if (o < FO) outA[(size_t)a * FO + o] = relu_(acc[r][c] + bsh[o]);
            }
        }
    }
}

// =====================================================================
// launch
// =====================================================================
extern "C" void kernel_launch(void* const* d_in, const int* in_sizes, int n_in,
                              void* d_out, int out_size)
{
    const float* af    = (const float*)d_in[0];
    const float* pf    = (const float*)d_in[1];
    const int*   split = (const int*)  d_in[2];
    const int*   atp   = (const int*)  d_in[3];
    const float* W_AA  = (const float*)d_in[4];
    const float* b_AA  = (const float*)d_in[5];
    const float* W_PA  = (const float*)d_in[6];
    const float* b_PA  = (const float*)d_in[7];
    const float* W_A   = (const float*)d_in[8];
    const float* b_A   = (const float*)d_in[9];
    const float* W_AP  = (const float*)d_in[10];
    const float* b_AP  = (const float*)d_in[11];
    const float* W_PP  = (const float*)d_in[12];
    const float* b_PP  = (const float*)d_in[13];
    const float* W_P   = (const float*)d_in[14];
    const float* b_P   = (const float*)d_in[15];
    float* out = (float*)d_out;

    cudaFuncSetAttribute(pair_kernel, cudaFuncAttributeMaxDynamicSharedMemorySize, PAIR_SMEM_BYTES);
    cudaFuncSetAttribute(atom_out_kernel, cudaFuncAttributeMaxDynamicSharedMemorySize, K3_SMEM_BYTES);

    dim3 g1((NA + 63) / 64, 3);
    atom_pre_kernel<<<g1, 256>>>(af, W_AA, b_AA, W_AP);

    pair_kernel<<<NP / 128, 256, PAIR_SMEM_BYTES>>>(
        pf, split, atp, W_PA, b_PA, W_PP, b_PP, W_P, b_P, b_AP,
        out + (size_t)NA * FO);

    atom_out_kernel<<<(NA + 63) / 64, 256, K3_SMEM_BYTES>>>(W_A, b_A, out);
}

// round 3
// speedup vs baseline: 1.0941x; 1.0941x over previous
#include <cuda_runtime.h>

#define NA 100000
#define NP 3200000
#define FA 75
#define FPR 14
#define HH 50
#define FO 50

// ---------------- scratch (device globals; no allocs allowed) ----------------
__device__ float g_AA[NA * HH];   // relu(af @ W_AA^T + b_AA)
__device__ float g_X1[NA * HH];   // af @ W_AP[:, :75]^T   (no bias)
__device__ float g_X2[NA * HH];   // af @ W_AP[:, 75:]^T   (no bias)
__device__ float g_PA[NA * HH];   // segment-summed relu(pf @ W_PA^T + b_PA)

__device__ __forceinline__ float relu_(float x) { return fmaxf(x, 0.0f); }

// packed fp32x2 FMA (Blackwell): d = a*b + d, lane-wise on 64-bit pairs
__device__ __forceinline__ void fma2_(unsigned long long& d,
                                      unsigned long long a,
                                      unsigned long long b) {
    asm("fma.rn.f32x2 %0, %1, %2, %0;" : "+l"(d) : "l"(a), "l"(b));
}
__device__ __forceinline__ unsigned long long dup_(float x) {
    unsigned long long r;
    asm("mov.b64 %0, {%1, %1};" : "=l"(r) : "f"(x));
    return r;
}
__device__ __forceinline__ float2 unpk_(unsigned long long v) {
    float2 f;
    asm("mov.b64 {%0, %1}, %2;" : "=f"(f.x), "=f"(f.y) : "l"(v));
    return f;
}

// =====================================================================
// K1: atom-side precompute, merged.  grid = ceil(NA/64), 256 threads.
// One block: stage A[64x76] once, then 3 sequential 64x64 GEMMs:
//   mat 0: g_AA = relu(af @ W_AA^T + b_AA)   (also zeroes g_PA)
//   mat 1: g_X1 = af @ W1^T
//   mat 2: g_X2 = af @ W2^T
// 4x4 per thread, fma.rn.f32x2 row-pairs.
// =====================================================================
__global__ __launch_bounds__(256) void atom_pre_kernel(
    const float* __restrict__ af,
    const float* __restrict__ W_AA, const float* __restrict__ b_AA,
    const float* __restrict__ W_AP)
{
    __shared__ __align__(16) float AsT[76 * 68];
    __shared__ __align__(16) float BsT[76 * 68];
    __shared__ float bsh[64];

    const int abase = blockIdx.x * 64;
    const int tid = threadIdx.x;

    for (int idx = tid; idx < 64 * 76; idx += 256) {
        int k = idx % 76, m = idx / 76;
        int a = abase + m;
        AsT[k * 68 + m] = (k < FA && a < NA) ? af[a * FA + k] : 0.0f;
    }
    for (int idx = tid; idx < 64 * HH; idx += 256) {
        int m = idx / HH, o = idx % HH;
        int a = abase + m;
        if (a < NA) g_PA[a * HH + o] = 0.0f;
    }
    if (tid < 64) bsh[tid] = (tid < HH) ? b_AA[tid] : 0.0f;

    const int tm = tid >> 4, tn = tid & 15;
    const int m0 = tm * 4, n0 = tn * 4;

    for (int mat = 0; mat < 3; mat++) {
        __syncthreads();   // covers AsT on iter 0, prior-GEMM reads after
        const float* W; int ws, wo;
        if (mat == 0) { W = W_AA; ws = FA;     wo = 0; }
        else          { W = W_AP; ws = 2 * FA; wo = (mat == 1) ? 0 : FA; }
        for (int idx = tid; idx < 64 * 76; idx += 256) {
            int k = idx % 76, o = idx / 76;
            BsT[k * 68 + o] = (k < FA && o < HH) ? W[o * ws + wo + k] : 0.0f;
        }
        __syncthreads();

        unsigned long long acc2[2][4];
#pragma unroll
        for (int rp = 0; rp < 2; rp++)
#pragma unroll
            for (int c = 0; c < 4; c++) acc2[rp][c] = 0ull;

#pragma unroll 4
        for (int k = 0; k < 76; k++) {
            ulonglong2 a2 = *(const ulonglong2*)&AsT[k * 68 + m0];
            float4 b4 = *(const float4*)&BsT[k * 68 + n0];
            unsigned long long av[2] = {a2.x, a2.y};
            unsigned long long bd[4] = {dup_(b4.x), dup_(b4.y), dup_(b4.z), dup_(b4.w)};
#pragma unroll
            for (int rp = 0; rp < 2; rp++)
#pragma unroll
                for (int c = 0; c < 4; c++) fma2_(acc2[rp][c], av[rp], bd[c]);
        }

        float* dst = (mat == 0) ? g_AA : ((mat == 1) ? g_X1 : g_X2);
#pragma unroll
        for (int rp = 0; rp < 2; rp++) {
#pragma unroll
            for (int c = 0; c < 4; c++) {
                int o = n0 + c;
                if (o < HH) {
                    float2 f2 = unpk_(acc2[rp][c]);
                    int a0 = abase + m0 + 2 * rp;
                    if (mat == 0) {
                        f2.x = relu_(f2.x + bsh[o]);
                        f2.y = relu_(f2.y + bsh[o]);
                    }
                    if (a0 < NA)     dst[(size_t)a0 * HH + o]       = f2.x;
                    if (a0 + 1 < NA) dst[(size_t)(a0 + 1) * HH + o] = f2.y;
                }
            }
        }
    }
}

// =====================================================================
// K2 (megakernel), 128-pair tiles, 256 threads, 2 blocks/SM.
// Inner GEMMs use fma.rn.f32x2 (row-pair packed accumulators).
// =====================================================================
#define CTS 132
#define WTS 68
#define PAIR_SMEM_FLOATS (104*CTS + 104*WTS + 16*CTS + 16*WTS + 16*WTS + 4*52 + 256 + 132 + 128 + 4)
#define PAIR_SMEM_BYTES  (PAIR_SMEM_FLOATS * 4)

__global__ __launch_bounds__(256, 2) void pair_kernel(
    const float* __restrict__ pf,
    const int*   __restrict__ split,
    const int*   __restrict__ atp,
    const float* __restrict__ W_PA, const float* __restrict__ b_PA,
    const float* __restrict__ W_PP, const float* __restrict__ b_PP,
    const float* __restrict__ W_P,  const float* __restrict__ b_P,
    const float* __restrict__ b_AP,
    float* __restrict__ outP)
{
    extern __shared__ __align__(16) float sm[];
    float* CT   = sm;                       // [104][CTS]
    float* WT   = CT + 104 * CTS;           // [104][WTS]
    float* pfT  = WT + 104 * WTS;           // [16][CTS]
    float* WpaT = pfT + 16 * CTS;           // [16][WTS]
    float* WppT = WpaT + 16 * WTS;          // [16][WTS]
    float* sbAP = WppT + 16 * WTS;          // 52
    float* sbPP = sbAP + 52;
    float* sbPA = sbPP + 52;
    float* sbP  = sbPA + 52;
    int* sidx   = (int*)(sbP + 52);         // 256
    int* spsv   = sidx + 256;               // 132
    int* sheads = spsv + 132;               // 128
    int* snh    = sheads + 128;             // 1

    const int p0  = blockIdx.x * 128;
    const int tid = threadIdx.x;

    // ---------------- P0: staging ----------------
    for (int idx = tid; idx < 128 * 16; idx += 256) {
        int kk = idx & 15, p = idx >> 4;
        pfT[kk * CTS + p] = (kk < FPR) ? __ldcs(&pf[(p0 + p) * FPR + kk]) : 0.0f;
    }
    for (int idx = tid; idx < 64 * 104; idx += 256) {
        int k = idx % 104, o = idx / 104;
        WT[k * WTS + o] = (k < 2 * HH && o < FO) ? W_P[o * 2 * HH + k] : 0.0f;
    }
    for (int idx = tid; idx < 64 * 16; idx += 256) {
        int k = idx & 15, o = idx >> 4;
        bool v = (k < FPR && o < HH);
        WpaT[k * WTS + o] = v ? W_PA[o * FPR + k] : 0.0f;
        WppT[k * WTS + o] = v ? W_PP[o * FPR + k] : 0.0f;
    }
    if (tid < 52) {
        float vAP = (tid < HH) ? b_AP[tid] : 0.0f;
        float vPP = (tid < HH) ? b_PP[tid] : 0.0f;
        float vPA = (tid < HH) ? b_PA[tid] : 0.0f;
        float vP  = (tid < FO) ? b_P[tid]  : 0.0f;
        sbAP[tid] = vAP; sbPP[tid] = vPP; sbPA[tid] = vPA; sbP[tid] = vP;
    }
    sidx[tid] = atp[p0 * 2 + tid];
    if (tid < 129) {
        // spsv[0] = -1 ALWAYS: forces a run head at t=0 of every tile, so
        // runs crossing tile boundaries are accumulated from both sides.
        spsv[tid] = (tid == 0) ? -1 : split[p0 + tid - 1];
    }
    if (tid == 0) *snh = 0;
    __syncthreads();

    const int tm = tid >> 4, tn = tid & 15;
    const int m0 = tm * 8, n0 = tn * 4;

    // ---------------- P1: PA (into CT rows [0,50) as scratch) ----------------
    {
        unsigned long long acc2[4][4];
#pragma unroll
        for (int rp = 0; rp < 4; rp++)
#pragma unroll
            for (int c = 0; c < 4; c++) acc2[rp][c] = 0ull;
#pragma unroll
        for (int k = 0; k < 16; k++) {
            float4 b4 = *(const float4*)&WpaT[k * WTS + n0];
            ulonglong2 a01 = *(const ulonglong2*)&pfT[k * CTS + m0];
            ulonglong2 a23 = *(const ulonglong2*)&pfT[k * CTS + m0 + 4];
            unsigned long long av[4] = {a01.x, a01.y, a23.x, a23.y};
            unsigned long long bd[4] = {dup_(b4.x), dup_(b4.y), dup_(b4.z), dup_(b4.w)};
#pragma unroll
            for (int rp = 0; rp < 4; rp++)
#pragma unroll
                for (int c = 0; c < 4; c++) fma2_(acc2[rp][c], av[rp], bd[c]);
        }
#pragma unroll
        for (int c = 0; c < 4; c++) {
            int o = n0 + c;
            if (o < HH) {
                float b = sbPA[o];
#pragma unroll
                for (int rp = 0; rp < 4; rp++) {
                    float2 f2 = unpk_(acc2[rp][c]);
                    CT[o * CTS + m0 + 2 * rp]     = relu_(f2.x + b);
                    CT[o * CTS + m0 + 2 * rp + 1] = relu_(f2.y + b);
                }
            }
        }
    }
    __syncthreads();

    // ---------------- P2: sorted-run reduce + atomics into g_PA ----------------
    if (tid < 128) {
        if (spsv[tid + 1] != spsv[tid]) {
            int pos = atomicAdd(snh, 1);
            sheads[pos] = tid;
        }
    }
    __syncthreads();
    {
        int nh = *snh;
        for (int t = tid; t < nh * 64; t += 256) {
            int o = t & 63, hi = t >> 6;
            if (o < HH) {
                int h = sheads[hi];
                int seg = spsv[h + 1];
                float s = 0.0f;
                int q = h;
                while (q < 128 && spsv[q + 1] == seg) { s += CT[o * CTS + q]; q++; }
                atomicAdd(&g_PA[seg * HH + o], s);
            }
        }
    }
    __syncthreads();

    // ---------------- P3: S gathers + PP GEMM ----------------
    for (int idx = tid; idx < 128 * 25; idx += 256) {
        int p = idx / 25, k2 = idx % 25;
        int k = k2 * 2;
        int i = sidx[2 * p], j = sidx[2 * p + 1];
        float2 x1i = *(const float2*)&g_X1[i * HH + k];
        float2 x2j = *(const float2*)&g_X2[j * HH + k];
        float2 x1j = *(const float2*)&g_X1[j * HH + k];
        float2 x2i = *(const float2*)&g_X2[i * HH + k];
        float b0 = sbAP[k], b1 = sbAP[k + 1];
        float s0 = relu_(x1i.x + x2j.x + b0) + relu_(x1j.x + x2i.x + b0);
        float s1 = relu_(x1i.y + x2j.y + b1) + relu_(x1j.y + x2i.y + b1);
        CT[k * CTS + p]       = s0;
        CT[(k + 1) * CTS + p] = s1;
    }
    for (int idx = tid; idx < 4 * 128; idx += 256)
        CT[(100 + (idx >> 7)) * CTS + (idx & 127)] = 0.0f;
    {
        unsigned long long acc2[4][4];
#pragma unroll
        for (int rp = 0; rp < 4; rp++)
#pragma unroll
            for (int c = 0; c < 4; c++) acc2[rp][c] = 0ull;
#pragma unroll
        for (int k = 0; k < 16; k++) {
            float4 b4 = *(const float4*)&WppT[k * WTS + n0];
            ulonglong2 a01 = *(const ulonglong2*)&pfT[k * CTS + m0];
            ulonglong2 a23 = *(const ulonglong2*)&pfT[k * CTS + m0 + 4];
            unsigned long long av[4] = {a01.x, a01.y, a23.x, a23.y};
            unsigned long long bd[4] = {dup_(b4.x), dup_(b4.y), dup_(b4.z), dup_(b4.w)};
#pragma unroll
            for (int rp = 0; rp < 4; rp++)
#pragma unroll
                for (int c = 0; c < 4; c++) fma2_(acc2[rp][c], av[rp], bd[c]);
        }
#pragma unroll
        for (int c = 0; c < 4; c++) {
            int o = n0 + c;
            if (o < HH) {
                float b = sbPP[o];
#pragma unroll
                for (int rp = 0; rp < 4; rp++) {
                    float2 f2 = unpk_(acc2[rp][c]);
                    CT[(HH + o) * CTS + m0 + 2 * rp]     = relu_(f2.x + b);
                    CT[(HH + o) * CTS + m0 + 2 * rp + 1] = relu_(f2.y + b);
                }
            }
        }
    }
    __syncthreads();

    // ---------------- P4: P = relu([S|PP] @ W_P^T + b_P) ----------------
    {
        unsigned long long acc2[4][4];
#pragma unroll
        for (int rp = 0; rp < 4; rp++)
#pragma unroll
            for (int c = 0; c < 4; c++) acc2[rp][c] = 0ull;
#pragma unroll 4
        for (int k = 0; k < 104; k++) {
            float4 b4 = *(const float4*)&WT[k * WTS + n0];
            ulonglong2 a01 = *(const ulonglong2*)&CT[k * CTS + m0];
            ulonglong2 a23 = *(const ulonglong2*)&CT[k * CTS + m0 + 4];
            unsigned long long av[4] = {a01.x, a01.y, a23.x, a23.y};
            unsigned long long bd[4] = {dup_(b4.x), dup_(b4.y), dup_(b4.z), dup_(b4.w)};
#pragma unroll
            for (int rp = 0; rp < 4; rp++)
#pragma unroll
                for (int c = 0; c < 4; c++) fma2_(acc2[rp][c], av[rp], bd[c]);
        }
        if (n0 < FO) {
            float accf[8][4];
#pragma unroll
            for (int rp = 0; rp < 4; rp++)
#pragma unroll
                for (int c = 0; c < 4; c++) {
                    float2 f2 = unpk_(acc2[rp][c]);
                    accf[2 * rp][c]     = f2.x;
                    accf[2 * rp + 1][c] = f2.y;
                }
            float bb[4];
#pragma unroll
            for (int c = 0; c < 4; c++) bb[c] = sbP[n0 + c];
#pragma unroll
            for (int r = 0; r < 8; r++) {
                size_t p = (size_t)(p0 + m0 + r);
                float v0 = relu_(accf[r][0] + bb[0]);
                float v1 = relu_(accf[r][1] + bb[1]);
                float* dst = &outP[p * FO + n0];
                __stcs((float2*)dst, make_float2(v0, v1));
                if (n0 + 3 < FO) {
                    float v2 = relu_(accf[r][2] + bb[2]);
                    float v3 = relu_(accf[r][3] + bb[3]);
                    __stcs((float2*)(dst + 2), make_float2(v2, v3));
                }
            }
        }
    }
}

// =====================================================================
// K3: A = relu(concat([AA, PAseg]) @ W_A^T + b_A)
// =====================================================================
#define K3_SMEM_FLOATS (104*68 * 2 + 64)
#define K3_SMEM_BYTES  (K3_SMEM_FLOATS * 4)

__global__ __launch_bounds__(256) void atom_out_kernel(
    const float* __restrict__ W_A, const float* __restrict__ b_A,
    float* __restrict__ outA)
{
    extern __shared__ __align__(16) float sm3[];
    float* CcT = sm3;             // [104][68]
    float* BsT = CcT + 104 * 68;  // [104][68]
    float* bsh = BsT + 104 * 68;  // 64

    const int abase = blockIdx.x * 64;
    const int tid = threadIdx.x;

    for (int idx = tid; idx < 64 * 104; idx += 256) {
        int k = idx % 104, m = idx / 104;
        int a = abase + m;
        float v = 0.0f;
        if (a < NA) {
            if (k < HH)          v = g_AA[a * HH + k];
            else if (k < 2 * HH) v = g_PA[a * HH + (k - HH)];
        }
        CcT[k * 68 + m] = v;
    }
    for (int idx = tid; idx < 64 * 104; idx += 256) {
        int k = idx % 104, o = idx / 104;
        BsT[k * 68 + o] = (k < 2 * HH && o < FO) ? W_A[o * 2 * HH + k] : 0.0f;
    }
    if (tid < 64) bsh[tid] = (tid < FO) ? b_A[tid] : 0.0f;
    __syncthreads();

    const int tm = tid >> 4, tn = tid & 15;
    const int m0 = tm * 4, n0 = tn * 4;
    unsigned long long acc2[2][4];
#pragma unroll
    for (int rp = 0; rp < 2; rp++)
#pragma unroll
        for (int c = 0; c < 4; c++) acc2[rp][c] = 0ull;

#pragma unroll 4
    for (int k = 0; k < 104; k++) {
        ulonglong2 a2 = *(const ulonglong2*)&CcT[k * 68 + m0];
        float4 b4 = *(const float4*)&BsT[k * 68 + n0];
        unsigned long long av[2] = {a2.x, a2.y};
        unsigned long long bd[4] = {dup_(b4.x), dup_(b4.y), dup_(b4.z), dup_(b4.w)};
#pragma unroll
        for (int rp = 0; rp < 2; rp++)
#pragma unroll
            for (int c = 0; c < 4; c++) fma2_(acc2[rp][c], av[rp], bd[c]);
    }
#pragma unroll
    for (int rp = 0; rp < 2; rp++) {
#pragma unroll
        for (int c = 0; c < 4; c++) {
            int o = n0 + c;
            if (o < FO) {
                float2 f2 = unpk_(acc2[rp][c]);
                int a0 = abase + m0 + 2 * rp;
                if (a0 < NA)     outA[(size_t)a0 * FO + o]       = relu_(f2.x + bsh[o]);
                if (a0 + 1 < NA) outA[(size_t)(a0 + 1) * FO + o] = relu_(f2.y + bsh[o]);
            }
        }
    }
}

// =====================================================================
// launch
// =====================================================================
extern "C" void kernel_launch(void* const* d_in, const int* in_sizes, int n_in,
                              void* d_out, int out_size)
{
    const float* af    = (const float*)d_in[0];
    const float* pf    = (const float*)d_in[1];
    const int*   split = (const int*)  d_in[2];
    const int*   atp   = (const int*)  d_in[3];
    const float* W_AA  = (const float*)d_in[4];
    const float* b_AA  = (const float*)d_in[5];
    const float* W_PA  = (const float*)d_in[6];
    const float* b_PA  = (const float*)d_in[7];
    const float* W_A   = (const float*)d_in[8];
    const float* b_A   = (const float*)d_in[9];
    const float* W_AP  = (const float*)d_in[10];
    const float* b_AP  = (const float*)d_in[11];
    const float* W_PP  = (const float*)d_in[12];
    const float* b_PP  = (const float*)d_in[13];
    const float* W_P   = (const float*)d_in[14];
    const float* b_P   = (const float*)d_in[15];
    float* out = (float*)d_out;

    cudaFuncSetAttribute(pair_kernel, cudaFuncAttributeMaxDynamicSharedMemorySize, PAIR_SMEM_BYTES);
    cudaFuncSetAttribute(atom_out_kernel, cudaFuncAttributeMaxDynamicSharedMemorySize, K3_SMEM_BYTES);

    atom_pre_kernel<<<(NA + 63) / 64, 256>>>(af, W_AA, b_AA, W_AP);

    pair_kernel<<<NP / 128, 256, PAIR_SMEM_BYTES>>>(
        pf, split, atp, W_PA, b_PA, W_PP, b_PP, W_P, b_P, b_AP,
        out + (size_t)NA * FO);

    atom_out_kernel<<<(NA + 63) / 64, 256, K3_SMEM_BYTES>>>(W_A, b_A, out);
}